// round 10
// baseline (speedup 1.0000x reference)
#include <cuda_runtime.h>
#include <cstdint>
#include <cstddef>

// BertBiLstmCrf: BiLSTM(768->2x384) -> FC(768->12) -> Viterbi
// B=64, T=512, H=768, LH=384, L=12. Output: [score(64); path(64*512)] f32.
// Hot paths use packed fp32 FMA (fma.rn.f32x2, Blackwell sm_100+).

#define NEGV (-1000.0f)

__device__ float        g_pre[(size_t)32768 * 3072];   // [t*64+b][dir*1536+row]
__device__ float        g_h[2][512][384][64];          // [dir][t][k][b]
__device__ float        g_feat[512][64][12];
__device__ unsigned char g_ptr[511][64][12];
__device__ unsigned int g_bar[8];

__global__ void k_init() { if (threadIdx.x < 8) g_bar[threadIdx.x] = 0u; }

// ---- packed f32x2 helpers -------------------------------------------------
__device__ __forceinline__ void fma2(unsigned long long &d,
                                     unsigned long long a, unsigned long long b)
{
    asm("fma.rn.f32x2 %0, %1, %2, %0;" : "+l"(d) : "l"(a), "l"(b));
}
__device__ __forceinline__ float2 up2(unsigned long long v)
{
    float2 f; asm("mov.b64 {%0, %1}, %2;" : "=f"(f.x), "=f"(f.y) : "l"(v));
    return f;
}

// ---------------------------------------------------------------------------
// Kernel 1: input-projection GEMM, FFMA2.
// C[m][n] = sum_k A[m][k]*W[n][k] + bias[n]; m = t*64+b (A row = hs[b][t]),
// n<1536 forward weights, else backward. M=32768, N=3072, K=768.
// CTA 128x128, BK=8, 256 thr, 8x8 per thread (as 8 x 4 f32x2 pairs over n).
// A is stored DUPLICATED in smem ((a,a) pairs) so no packing in inner loop.
// ---------------------------------------------------------------------------
__global__ __launch_bounds__(256) void k_gemm(
    const float* __restrict__ hs,
    const float* __restrict__ wf, const float* __restrict__ wb,
    const float* __restrict__ bif, const float* __restrict__ bhf,
    const float* __restrict__ bib, const float* __restrict__ bhb)
{
    __shared__ __align__(16) float As[8][256];   // dup pairs: [k][2m]
    __shared__ __align__(16) float Bs[8][128];   // [k][n]
    const int tid = threadIdx.x;
    const int m0 = blockIdx.y * 128;
    const int n0 = blockIdx.x * 128;

    const int lr = tid >> 1;           // tile row 0..127
    const int lk = (tid & 1) * 4;      // k offset 0 or 4
    const int m  = m0 + lr;
    const float* arow = hs + ((size_t)(m & 63) * 512 + (m >> 6)) * 768 + lk;
    const int nrow = n0 + lr;
    const float* brow = (nrow < 1536) ? (wf + (size_t)nrow * 768 + lk)
                                      : (wb + (size_t)(nrow - 1536) * 768 + lk);

    const int ty = tid >> 4, tx = tid & 15;

    unsigned long long acc2[8][4];
#pragma unroll
    for (int i = 0; i < 8; i++)
#pragma unroll
        for (int j = 0; j < 4; j++) acc2[i][j] = 0ULL;

    float4 a4 = *(const float4*)(arow);
    float4 b4 = *(const float4*)(brow);

    for (int k0 = 0; k0 < 768; k0 += 8) {
        {   // store current tile (A duplicated)
            float2 d;
            d.x = a4.x; d.y = a4.x; *(float2*)&As[lk+0][2*lr] = d;
            d.x = a4.y; d.y = a4.y; *(float2*)&As[lk+1][2*lr] = d;
            d.x = a4.z; d.y = a4.z; *(float2*)&As[lk+2][2*lr] = d;
            d.x = a4.w; d.y = a4.w; *(float2*)&As[lk+3][2*lr] = d;
            Bs[lk+0][lr] = b4.x; Bs[lk+1][lr] = b4.y;
            Bs[lk+2][lr] = b4.z; Bs[lk+3][lr] = b4.w;
        }
        __syncthreads();
        if (k0 + 8 < 768) {
            a4 = *(const float4*)(arow + k0 + 8);
            b4 = *(const float4*)(brow + k0 + 8);
        }
#pragma unroll
        for (int kk = 0; kk < 8; kk++) {
            ulonglong2 aU0 = *(const ulonglong2*)&As[kk][16*ty + 0];
            ulonglong2 aU1 = *(const ulonglong2*)&As[kk][16*ty + 4];
            ulonglong2 aU2 = *(const ulonglong2*)&As[kk][16*ty + 8];
            ulonglong2 aU3 = *(const ulonglong2*)&As[kk][16*ty + 12];
            ulonglong2 bU0 = *(const ulonglong2*)&Bs[kk][8*tx + 0];
            ulonglong2 bU1 = *(const ulonglong2*)&Bs[kk][8*tx + 4];
            unsigned long long a2[8] = { aU0.x, aU0.y, aU1.x, aU1.y,
                                         aU2.x, aU2.y, aU3.x, aU3.y };
            unsigned long long b2[4] = { bU0.x, bU0.y, bU1.x, bU1.y };
#pragma unroll
            for (int i = 0; i < 8; i++)
#pragma unroll
                for (int j = 0; j < 4; j++)
                    fma2(acc2[i][j], a2[i], b2[j]);
        }
        __syncthreads();
    }

    float bias[8];
#pragma unroll
    for (int j = 0; j < 8; j++) {
        int n = n0 + tx*8 + j;
        bias[j] = (n < 1536) ? (bif[n] + bhf[n]) : (bib[n - 1536] + bhb[n - 1536]);
    }
#pragma unroll
    for (int i = 0; i < 8; i++) {
        size_t row = (size_t)(m0 + ty*8 + i) * 3072 + (size_t)(n0 + tx*8);
        float2 f0 = up2(acc2[i][0]);
        float2 f1 = up2(acc2[i][1]);
        float2 f2 = up2(acc2[i][2]);
        float2 f3 = up2(acc2[i][3]);
        float4 v0, v1;
        v0.x = f0.x + bias[0]; v0.y = f0.y + bias[1];
        v0.z = f1.x + bias[2]; v0.w = f1.y + bias[3];
        v1.x = f2.x + bias[4]; v1.y = f2.y + bias[5];
        v1.z = f3.x + bias[6]; v1.w = f3.y + bias[7];
        *(float4*)&g_pre[row]     = v0;
        *(float4*)&g_pre[row + 4] = v1;
    }
}

// ---------------------------------------------------------------------------
// Kernel 2: persistent BiLSTM recurrence, FFMA2 (lanes = k-even/k-odd).
// 128 blocks (dir[2] x kgroup[16] x bgroup[4]) x 128 thr, 1 block/SM.
// h_s is stored transposed [b][k] (pad 396) so k-pairs load contiguously;
// w_s rows are k-contiguous -> both FMA2 operands come free, zero packing.
// ---------------------------------------------------------------------------
__device__ __forceinline__ float sigf(float x) { return 1.f / (1.f + expf(-x)); }

#define REC_SMEM_FLOATS (96*388 + 16*396 + 96*17 + 384)

__global__ __launch_bounds__(128) void k_rec(
    const float* __restrict__ whf, const float* __restrict__ whb,
    const float* __restrict__ h0, const float* __restrict__ c0)
{
    extern __shared__ float sm[];
    float* w_s    = sm;                 // [96][388]  rows: gate*24+kk, cols k
    float* h_s    = sm + 96*388;        // [16][396]  h_prev[b][k] (transposed)
    float* gate_s = h_s + 16*396;       // [96][17]
    float* c_s    = gate_s + 96*17;     // [24*16]

    const int bid = blockIdx.x;
    const int dir = bid >> 6;
    const int kg  = (bid >> 2) & 15;
    const int bg  = bid & 3;
    const int k0  = kg * 24, b0 = bg * 16;
    const int tid = threadIdx.x;
    const float* whh = dir ? whb : whf;

    for (int idx = tid; idx < 96*96; idx += 128) {
        int r = idx / 96, cq = (idx - r*96) * 4;
        int gate = r / 24, kk = r - gate*24;
        float4 v = *(const float4*)(whh + (size_t)(gate*384 + k0 + kk) * 384 + cq);
        *(float4*)&w_s[r*388 + cq] = v;
    }
    for (int idx = tid; idx < 384; idx += 128) {
        int kk = idx >> 4, b = idx & 15;
        c_s[idx] = c0[((size_t)dir*64 + b0 + b) * 384 + k0 + kk];
    }
    __syncthreads();

    const int rg = tid >> 2;   // 0..31 -> rows 3rg..3rg+2
    const int bq = tid & 3;    // 0..3  -> batches 4bq..4bq+3
    const float* wr0 = w_s + (3*rg + 0) * 388;
    const float* wr1 = w_s + (3*rg + 1) * 388;
    const float* wr2 = w_s + (3*rg + 2) * 388;
    const float* hr0 = h_s + (bq*4 + 0) * 396;
    const float* hr1 = h_s + (bq*4 + 1) * 396;
    const float* hr2 = h_s + (bq*4 + 2) * 396;
    const float* hr3 = h_s + (bq*4 + 3) * 396;
    int grow[3];
#pragma unroll
    for (int i = 0; i < 3; i++) {
        int r = 3*rg + i;
        grow[i] = dir*1536 + (r/24)*384 + k0 + (r - (r/24)*24);
    }
    volatile unsigned int* bar = &g_bar[dir*4 + bg];

    // prefetched x-projection + biases for current step
    float pre[3][4];
    {
        const int t0 = dir ? 511 : 0;
#pragma unroll
        for (int i = 0; i < 3; i++)
#pragma unroll
            for (int j = 0; j < 4; j++)
                pre[i][j] = g_pre[((size_t)t0*64 + b0 + 4*bq + j) * 3072 + grow[i]];
    }

    for (int s = 0; s < 512; s++) {
        const int t = dir ? (511 - s) : s;

        // fill h_prev transposed [b][k]
        if (s == 0) {
#pragma unroll 1
            for (int b = 0; b < 16; b++)
                for (int k = tid; k < 384; k += 128)
                    h_s[b*396 + k] = h0[((size_t)dir*64 + b0 + b) * 384 + k];
        } else {
            const int tp = dir ? (t + 1) : (t - 1);
            const float* hp = &g_h[dir][tp][0][b0];
            for (int idx = tid; idx < 384*4; idx += 128) {
                int k = idx >> 2, q = idx & 3;
                float4 v = *(const float4*)(hp + (size_t)k*64 + q*4);
                h_s[(q*4+0)*396 + k] = v.x;
                h_s[(q*4+1)*396 + k] = v.y;
                h_s[(q*4+2)*396 + k] = v.z;
                h_s[(q*4+3)*396 + k] = v.w;
            }
        }
        __syncthreads();

        unsigned long long acc2[3][4];
#pragma unroll
        for (int i = 0; i < 3; i++)
#pragma unroll
            for (int j = 0; j < 4; j++) acc2[i][j] = 0ULL;

#pragma unroll 2
        for (int k = 0; k < 384; k += 4) {
            ulonglong2 W0 = *(const ulonglong2*)(wr0 + k);
            ulonglong2 W1 = *(const ulonglong2*)(wr1 + k);
            ulonglong2 W2 = *(const ulonglong2*)(wr2 + k);
            ulonglong2 H0 = *(const ulonglong2*)(hr0 + k);
            ulonglong2 H1 = *(const ulonglong2*)(hr1 + k);
            ulonglong2 H2 = *(const ulonglong2*)(hr2 + k);
            ulonglong2 H3 = *(const ulonglong2*)(hr3 + k);
            fma2(acc2[0][0], W0.x, H0.x); fma2(acc2[0][0], W0.y, H0.y);
            fma2(acc2[0][1], W0.x, H1.x); fma2(acc2[0][1], W0.y, H1.y);
            fma2(acc2[0][2], W0.x, H2.x); fma2(acc2[0][2], W0.y, H2.y);
            fma2(acc2[0][3], W0.x, H3.x); fma2(acc2[0][3], W0.y, H3.y);
            fma2(acc2[1][0], W1.x, H0.x); fma2(acc2[1][0], W1.y, H0.y);
            fma2(acc2[1][1], W1.x, H1.x); fma2(acc2[1][1], W1.y, H1.y);
            fma2(acc2[1][2], W1.x, H2.x); fma2(acc2[1][2], W1.y, H2.y);
            fma2(acc2[1][3], W1.x, H3.x); fma2(acc2[1][3], W1.y, H3.y);
            fma2(acc2[2][0], W2.x, H0.x); fma2(acc2[2][0], W2.y, H0.y);
            fma2(acc2[2][1], W2.x, H1.x); fma2(acc2[2][1], W2.y, H1.y);
            fma2(acc2[2][2], W2.x, H2.x); fma2(acc2[2][2], W2.y, H2.y);
            fma2(acc2[2][3], W2.x, H3.x); fma2(acc2[2][3], W2.y, H3.y);
        }
#pragma unroll
        for (int i = 0; i < 3; i++)
#pragma unroll
            for (int j = 0; j < 4; j++) {
                float2 f = up2(acc2[i][j]);
                gate_s[(3*rg + i)*17 + 4*bq + j] = pre[i][j] + (f.x + f.y);
            }
        __syncthreads();

        // elementwise LSTM cell update (gate order i,f,g,o)
        for (int idx = tid; idx < 384; idx += 128) {
            int kk = idx >> 4, b = idx & 15;
            float gi = gate_s[(kk     )*17 + b];
            float gf = gate_s[(kk + 24)*17 + b];
            float gg = gate_s[(kk + 48)*17 + b];
            float go = gate_s[(kk + 72)*17 + b];
            float c = sigf(gf) * c_s[idx] + sigf(gi) * tanhf(gg);
            c_s[idx] = c;
            g_h[dir][t][k0 + kk][b0 + b] = sigf(go) * tanhf(c);
        }
        __threadfence();
        __syncthreads();

        if (tid == 0) atomicAdd((unsigned int*)&g_bar[dir*4 + bg], 1u);

        // hide next step's g_pre latency behind the barrier
        if (s + 1 < 512) {
            const int tn = dir ? (510 - s) : (s + 1);
#pragma unroll
            for (int i = 0; i < 3; i++)
#pragma unroll
                for (int j = 0; j < 4; j++)
                    pre[i][j] = g_pre[((size_t)tn*64 + b0 + 4*bq + j) * 3072 + grow[i]];
        }
        if (tid == 0) {
            const unsigned int target = 16u * (unsigned)(s + 1);
            while (*bar < target) { }
            __threadfence();
        }
        __syncthreads();
    }
}

// ---------------------------------------------------------------------------
// Kernel 3: emissions
// ---------------------------------------------------------------------------
__global__ __launch_bounds__(256) void k_fc(const float* __restrict__ fcw,
                                            const float* __restrict__ fcb)
{
    __shared__ float wsh[12*768];
    __shared__ float bsh[12];
    const int t = blockIdx.x;
    const int tid = threadIdx.x;
    for (int i = tid; i < 12*768; i += 256) wsh[i] = fcw[i];
    if (tid < 12) bsh[tid] = fcb[tid];
    __syncthreads();

    for (int o = tid; o < 768; o += 256) {
        int l = o >> 6, b = o & 63;
        const float* wl  = &wsh[l*768];
        const float* hp0 = &g_h[0][t][0][b];
        const float* hp1 = &g_h[1][t][0][b];
        float s0 = 0.f, s1 = 0.f, s2 = 0.f, s3 = 0.f;
#pragma unroll 4
        for (int k = 0; k < 384; k += 4) {
            s0 = fmaf(hp0[(size_t)(k+0)*64], wl[k+0], s0);
            s1 = fmaf(hp0[(size_t)(k+1)*64], wl[k+1], s1);
            s2 = fmaf(hp0[(size_t)(k+2)*64], wl[k+2], s2);
            s3 = fmaf(hp0[(size_t)(k+3)*64], wl[k+3], s3);
        }
#pragma unroll 4
        for (int k = 0; k < 384; k += 4) {
            s0 = fmaf(hp1[(size_t)(k+0)*64], wl[384+k+0], s0);
            s1 = fmaf(hp1[(size_t)(k+1)*64], wl[384+k+1], s1);
            s2 = fmaf(hp1[(size_t)(k+2)*64], wl[384+k+2], s2);
            s3 = fmaf(hp1[(size_t)(k+3)*64], wl[384+k+3], s3);
        }
        g_feat[t][b][l] = bsh[l] + ((s0 + s1) + (s2 + s3));
    }
}

// ---------------------------------------------------------------------------
// Kernel 4: Viterbi forward + backtrace (1 block, 768 threads)
// ---------------------------------------------------------------------------
__global__ __launch_bounds__(768) void k_vit(const float* __restrict__ trans,
                                             const int* __restrict__ start_idx,
                                             float* __restrict__ out)
{
    __shared__ float fvbuf[2][64][12];
    __shared__ float tr[12][12];
    const int tid = threadIdx.x;
    const int b = tid / 12, l = tid - b*12;

    if (tid < 144) tr[tid / 12][tid % 12] = trans[tid];
    const int s0 = *start_idx;
    fvbuf[0][b][l] = (l == s0) ? 0.f : NEGV;
    __syncthreads();

    float ft_next = g_feat[1][b][l];
    for (int t = 1; t < 512; t++) {
        const float* fv = fvbuf[(t - 1) & 1][b];
        float ft = ft_next;
        if (t < 511) ft_next = g_feat[t + 1][b][l];
        float best = tr[l][0] + fv[0];
        int arg = 0;
#pragma unroll
        for (int p = 1; p < 12; p++) {
            float sc = tr[l][p] + fv[p];
            if (sc > best) { best = sc; arg = p; }
        }
        fvbuf[t & 1][b][l] = best + ft;
        g_ptr[t - 1][b][l] = (unsigned char)arg;
        __syncthreads();
    }

    if (tid < 64) {
        const int bb = tid;
        float best = fvbuf[1][bb][0];
        int last = 0;
#pragma unroll
        for (int p = 1; p < 12; p++)
            if (fvbuf[1][bb][p] > best) { best = fvbuf[1][bb][p]; last = p; }
        out[bb] = best;
        float* path = out + 64 + (size_t)bb * 512;
        int cur = last;
        path[511] = (float)cur;
        for (int t = 510; t >= 0; t--) {
            cur = g_ptr[t][bb][cur];
            path[t] = (float)cur;
        }
    }
}

// ---------------------------------------------------------------------------
extern "C" void kernel_launch(void* const* d_in, const int* in_sizes, int n_in,
                              void* d_out, int out_size)
{
    const float* hs   = (const float*)d_in[0];
    const float* h0   = (const float*)d_in[1];
    const float* c0   = (const float*)d_in[2];
    const float* wihf = (const float*)d_in[3];
    const float* whhf = (const float*)d_in[4];
    const float* bihf = (const float*)d_in[5];
    const float* bhhf = (const float*)d_in[6];
    const float* wihb = (const float*)d_in[7];
    const float* whhb = (const float*)d_in[8];
    const float* bihb = (const float*)d_in[9];
    const float* bhhb = (const float*)d_in[10];
    const float* fcw  = (const float*)d_in[11];
    const float* fcb  = (const float*)d_in[12];
    const float* trans= (const float*)d_in[13];
    const int*   stp  = (const int*)d_in[14];
    (void)in_sizes; (void)n_in; (void)out_size;

    const size_t rec_smem = (size_t)REC_SMEM_FLOATS * sizeof(float); // 182,400 B
    cudaFuncSetAttribute(k_rec, cudaFuncAttributeMaxDynamicSharedMemorySize,
                         (int)rec_smem);

    k_init<<<1, 32>>>();

    dim3 gg(24, 256);
    k_gemm<<<gg, 256>>>(hs, wihf, wihb, bihf, bhhf, bihb, bhhb);

    k_rec<<<128, 128, rec_smem>>>(whhf, whhb, h0, c0);

    k_fc<<<512, 256>>>(fcw, fcb);

    k_vit<<<1, 768>>>(trans, stp, (float*)d_out);
}

// round 12
// speedup vs baseline: 1.0870x; 1.0870x over previous
#include <cuda_runtime.h>
#include <cstdint>
#include <cstddef>

// BertBiLstmCrf: BiLSTM(768->2x384) -> FC(768->12) -> Viterbi
// B=64, T=512, H=768, LH=384, L=12. Output: [score(64); path(64*512)] f32.
// All-fp32 FFMA implementation (tensor paths unavailable/slow on this target).

#define NEGV (-1000.0f)

__device__ float        g_pre[(size_t)32768 * 3072];   // [t*64+b][dir*1536+row]
__device__ float        g_h[2][512][384][64];          // [dir][t][k][b]
__device__ float        g_feat[512][64][12];
__device__ unsigned char g_ptr[511][64][12];
__device__ unsigned int g_bar[8];

__global__ void k_init() { if (threadIdx.x < 8) g_bar[threadIdx.x] = 0u; }

// ---------------------------------------------------------------------------
// Kernel 1: input-projection SGEMM, double-buffered, 2 CTAs/SM.
// C[m][n] = sum_k A[m][k]*W[n][k] + bias[n]; m = t*64+b (A row = hs[b][t]),
// n<1536 forward weights, else backward. M=32768, N=3072, K=768.
// CTA 128x128, BK=8, 256 thr, 8x8 per thread, ping-pong smem, 1 sync/iter.
// ---------------------------------------------------------------------------
__global__ __launch_bounds__(256, 2) void k_gemm(
    const float* __restrict__ hs,
    const float* __restrict__ wf, const float* __restrict__ wb,
    const float* __restrict__ bif, const float* __restrict__ bhf,
    const float* __restrict__ bib, const float* __restrict__ bhb)
{
    __shared__ float As[2][8][128];
    __shared__ float Bs[2][8][128];
    const int tid = threadIdx.x;
    const int m0 = blockIdx.y * 128;
    const int n0 = blockIdx.x * 128;

    const int lr = tid >> 1;           // tile row 0..127
    const int lk = (tid & 1) * 4;      // k offset 0 or 4
    const int m  = m0 + lr;
    const float* arow = hs + ((size_t)(m & 63) * 512 + (m >> 6)) * 768 + lk;
    const int nrow = n0 + lr;
    const float* brow = (nrow < 1536) ? (wf + (size_t)nrow * 768 + lk)
                                      : (wb + (size_t)(nrow - 1536) * 768 + lk);

    const int ty = tid >> 4, tx = tid & 15;

    float acc[8][8];
#pragma unroll
    for (int i = 0; i < 8; i++)
#pragma unroll
        for (int j = 0; j < 8; j++) acc[i][j] = 0.f;

    // prologue: tile 0 -> buffer 0
    float4 a4 = *(const float4*)(arow);
    float4 b4 = *(const float4*)(brow);
    As[0][lk+0][lr] = a4.x; As[0][lk+1][lr] = a4.y;
    As[0][lk+2][lr] = a4.z; As[0][lk+3][lr] = a4.w;
    Bs[0][lk+0][lr] = b4.x; Bs[0][lk+1][lr] = b4.y;
    Bs[0][lk+2][lr] = b4.z; Bs[0][lk+3][lr] = b4.w;
    __syncthreads();

    int cur = 0;
    for (int k0 = 8; k0 <= 768; k0 += 8) {
        const bool more = (k0 < 768);
        if (more) {                      // prefetch next tile (global)
            a4 = *(const float4*)(arow + k0);
            b4 = *(const float4*)(brow + k0);
        }
        // compute on buffer `cur` (overlaps LDG latency)
#pragma unroll
        for (int kk = 0; kk < 8; kk++) {
            float af[8], bf[8];
            *(float4*)(af)     = *(const float4*)&As[cur][kk][ty*8];
            *(float4*)(af + 4) = *(const float4*)&As[cur][kk][ty*8 + 4];
            *(float4*)(bf)     = *(const float4*)&Bs[cur][kk][tx*8];
            *(float4*)(bf + 4) = *(const float4*)&Bs[cur][kk][tx*8 + 4];
#pragma unroll
            for (int i = 0; i < 8; i++)
#pragma unroll
                for (int j = 0; j < 8; j++)
                    acc[i][j] = fmaf(af[i], bf[j], acc[i][j]);
        }
        if (more) {                      // fill the other buffer
            const int nxt = cur ^ 1;
            As[nxt][lk+0][lr] = a4.x; As[nxt][lk+1][lr] = a4.y;
            As[nxt][lk+2][lr] = a4.z; As[nxt][lk+3][lr] = a4.w;
            Bs[nxt][lk+0][lr] = b4.x; Bs[nxt][lk+1][lr] = b4.y;
            Bs[nxt][lk+2][lr] = b4.z; Bs[nxt][lk+3][lr] = b4.w;
        }
        __syncthreads();
        cur ^= 1;
    }

    float bias[8];
#pragma unroll
    for (int j = 0; j < 8; j++) {
        int n = n0 + tx*8 + j;
        bias[j] = (n < 1536) ? (bif[n] + bhf[n]) : (bib[n - 1536] + bhb[n - 1536]);
    }
#pragma unroll
    for (int i = 0; i < 8; i++) {
        size_t row = (size_t)(m0 + ty*8 + i) * 3072 + (size_t)(n0 + tx*8);
        float4 v0, v1;
        v0.x = acc[i][0] + bias[0]; v0.y = acc[i][1] + bias[1];
        v0.z = acc[i][2] + bias[2]; v0.w = acc[i][3] + bias[3];
        v1.x = acc[i][4] + bias[4]; v1.y = acc[i][5] + bias[5];
        v1.z = acc[i][6] + bias[6]; v1.w = acc[i][7] + bias[7];
        *(float4*)&g_pre[row]     = v0;
        *(float4*)&g_pre[row + 4] = v1;
    }
}

// ---------------------------------------------------------------------------
// Kernel 2: persistent BiLSTM recurrence. 128 blocks x 256 threads.
// Block = (dir, kgroup of 24 h-cols, bgroup of 16 batches); 1 block/SM.
// Thread = 3 gate-rows x 2 batches (bq, bq+8). h_s kept [k][16] (conflict-
// free scalar loads: bank = 16k+bq distinct per lane, rg-groups broadcast).
// W_hh slice cached in smem all 512 steps; h exchanged via g_h + atomic bar.
// ---------------------------------------------------------------------------
__device__ __forceinline__ float sigf(float x) { return 1.f / (1.f + expf(-x)); }

#define REC_SMEM_FLOATS (96*388 + 384*16 + 96*17 + 384)

__global__ __launch_bounds__(256) void k_rec(
    const float* __restrict__ whf, const float* __restrict__ whb,
    const float* __restrict__ h0, const float* __restrict__ c0)
{
    extern __shared__ float sm[];
    float* w_s    = sm;                 // [96][388]  rows: gate*24+kk, cols k
    float* h_s    = sm + 96*388;        // [384][16]  h_prev[k][b]
    float* gate_s = h_s + 384*16;       // [96][17]
    float* c_s    = gate_s + 96*17;     // [24*16]

    const int bid = blockIdx.x;
    const int dir = bid >> 6;
    const int kg  = (bid >> 2) & 15;
    const int bg  = bid & 3;
    const int k0  = kg * 24, b0 = bg * 16;
    const int tid = threadIdx.x;
    const float* whh = dir ? whb : whf;

    for (int idx = tid; idx < 96*96; idx += 256) {
        int r = idx / 96, cq = (idx - r*96) * 4;
        int gate = r / 24, kk = r - gate*24;
        float4 v = *(const float4*)(whh + (size_t)(gate*384 + k0 + kk) * 384 + cq);
        *(float4*)&w_s[r*388 + cq] = v;
    }
    for (int idx = tid; idx < 384; idx += 256) {
        int kk = idx >> 4, b = idx & 15;
        c_s[idx] = c0[((size_t)dir*64 + b0 + b) * 384 + k0 + kk];
    }
    __syncthreads();

    const int rg  = tid >> 3;   // 0..31 -> rows 3rg..3rg+2
    const int bq  = tid & 7;    // batches bq and bq+8
    const float* wr0 = w_s + (3*rg + 0) * 388;
    const float* wr1 = w_s + (3*rg + 1) * 388;
    const float* wr2 = w_s + (3*rg + 2) * 388;
    int grow[3];
#pragma unroll
    for (int i = 0; i < 3; i++) {
        int r = 3*rg + i;
        grow[i] = dir*1536 + (r/24)*384 + k0 + (r - (r/24)*24);
    }
    volatile unsigned int* bar = &g_bar[dir*4 + bg];

    // prefetched x-projection (+biases) for current step: 3 rows x 2 batches
    float pre[3][2];
    {
        const int t0 = dir ? 511 : 0;
#pragma unroll
        for (int i = 0; i < 3; i++) {
            pre[i][0] = g_pre[((size_t)t0*64 + b0 + bq    ) * 3072 + grow[i]];
            pre[i][1] = g_pre[((size_t)t0*64 + b0 + bq + 8) * 3072 + grow[i]];
        }
    }

    for (int s = 0; s < 512; s++) {
        const int t = dir ? (511 - s) : s;

        // fill h_prev [k][16]
        if (s == 0) {
            for (int idx = tid; idx < 384*16; idx += 256) {
                int k = idx >> 4, b = idx & 15;
                h_s[idx] = h0[((size_t)dir*64 + b0 + b) * 384 + k];
            }
        } else {
            const int tp = dir ? (t + 1) : (t - 1);
            const float* hp = &g_h[dir][tp][0][b0];
            for (int idx = tid; idx < 384*4; idx += 256) {
                int k = idx >> 2, q = idx & 3;
                float4 v = *(const float4*)(hp + (size_t)k*64 + q*4);
                *(float4*)&h_s[k*16 + q*4] = v;
            }
        }
        __syncthreads();

        float a00 = pre[0][0], a01 = pre[0][1];
        float a10 = pre[1][0], a11 = pre[1][1];
        float a20 = pre[2][0], a21 = pre[2][1];

#pragma unroll 2
        for (int k = 0; k < 384; k += 4) {
            float4 w0 = *(const float4*)(wr0 + k);
            float4 w1 = *(const float4*)(wr1 + k);
            float4 w2 = *(const float4*)(wr2 + k);
#pragma unroll
            for (int j = 0; j < 4; j++) {
                float hA = h_s[(k+j)*16 + bq];
                float hB = h_s[(k+j)*16 + bq + 8];
                float wj0 = ((const float*)&w0)[j];
                float wj1 = ((const float*)&w1)[j];
                float wj2 = ((const float*)&w2)[j];
                a00 = fmaf(wj0, hA, a00);  a01 = fmaf(wj0, hB, a01);
                a10 = fmaf(wj1, hA, a10);  a11 = fmaf(wj1, hB, a11);
                a20 = fmaf(wj2, hA, a20);  a21 = fmaf(wj2, hB, a21);
            }
        }
        gate_s[(3*rg + 0)*17 + bq    ] = a00;
        gate_s[(3*rg + 0)*17 + bq + 8] = a01;
        gate_s[(3*rg + 1)*17 + bq    ] = a10;
        gate_s[(3*rg + 1)*17 + bq + 8] = a11;
        gate_s[(3*rg + 2)*17 + bq    ] = a20;
        gate_s[(3*rg + 2)*17 + bq + 8] = a21;
        __syncthreads();

        // elementwise LSTM cell update (gate order i,f,g,o)
        for (int idx = tid; idx < 384; idx += 256) {
            int kk = idx >> 4, b = idx & 15;
            float gi = gate_s[(kk     )*17 + b];
            float gf = gate_s[(kk + 24)*17 + b];
            float gg = gate_s[(kk + 48)*17 + b];
            float go = gate_s[(kk + 72)*17 + b];
            float c = sigf(gf) * c_s[idx] + sigf(gi) * tanhf(gg);
            c_s[idx] = c;
            g_h[dir][t][k0 + kk][b0 + b] = sigf(go) * tanhf(c);
        }
        __threadfence();
        __syncthreads();

        if (tid == 0) atomicAdd((unsigned int*)&g_bar[dir*4 + bg], 1u);

        // hide next step's g_pre latency behind the barrier
        if (s + 1 < 512) {
            const int tn = dir ? (510 - s) : (s + 1);
#pragma unroll
            for (int i = 0; i < 3; i++) {
                pre[i][0] = g_pre[((size_t)tn*64 + b0 + bq    ) * 3072 + grow[i]];
                pre[i][1] = g_pre[((size_t)tn*64 + b0 + bq + 8) * 3072 + grow[i]];
            }
        }
        if (tid == 0) {
            const unsigned int target = 16u * (unsigned)(s + 1);
            while (*bar < target) { }
            __threadfence();
        }
        __syncthreads();
    }
}

// ---------------------------------------------------------------------------
// Kernel 3: emissions
// ---------------------------------------------------------------------------
__global__ __launch_bounds__(256) void k_fc(const float* __restrict__ fcw,
                                            const float* __restrict__ fcb)
{
    __shared__ float wsh[12*768];
    __shared__ float bsh[12];
    const int t = blockIdx.x;
    const int tid = threadIdx.x;
    for (int i = tid; i < 12*768; i += 256) wsh[i] = fcw[i];
    if (tid < 12) bsh[tid] = fcb[tid];
    __syncthreads();

    for (int o = tid; o < 768; o += 256) {
        int l = o >> 6, b = o & 63;
        const float* wl  = &wsh[l*768];
        const float* hp0 = &g_h[0][t][0][b];
        const float* hp1 = &g_h[1][t][0][b];
        float s0 = 0.f, s1 = 0.f, s2 = 0.f, s3 = 0.f;
#pragma unroll 4
        for (int k = 0; k < 384; k += 4) {
            s0 = fmaf(hp0[(size_t)(k+0)*64], wl[k+0], s0);
            s1 = fmaf(hp0[(size_t)(k+1)*64], wl[k+1], s1);
            s2 = fmaf(hp0[(size_t)(k+2)*64], wl[k+2], s2);
            s3 = fmaf(hp0[(size_t)(k+3)*64], wl[k+3], s3);
        }
#pragma unroll 4
        for (int k = 0; k < 384; k += 4) {
            s0 = fmaf(hp1[(size_t)(k+0)*64], wl[384+k+0], s0);
            s1 = fmaf(hp1[(size_t)(k+1)*64], wl[384+k+1], s1);
            s2 = fmaf(hp1[(size_t)(k+2)*64], wl[384+k+2], s2);
            s3 = fmaf(hp1[(size_t)(k+3)*64], wl[384+k+3], s3);
        }
        g_feat[t][b][l] = bsh[l] + ((s0 + s1) + (s2 + s3));
    }
}

// ---------------------------------------------------------------------------
// Kernel 4: Viterbi forward + backtrace (1 block, 768 threads)
// ---------------------------------------------------------------------------
__global__ __launch_bounds__(768) void k_vit(const float* __restrict__ trans,
                                             const int* __restrict__ start_idx,
                                             float* __restrict__ out)
{
    __shared__ float fvbuf[2][64][12];
    __shared__ float tr[12][12];
    const int tid = threadIdx.x;
    const int b = tid / 12, l = tid - b*12;

    if (tid < 144) tr[tid / 12][tid % 12] = trans[tid];
    const int s0 = *start_idx;
    fvbuf[0][b][l] = (l == s0) ? 0.f : NEGV;
    __syncthreads();

    float ft_next = g_feat[1][b][l];
    for (int t = 1; t < 512; t++) {
        const float* fv = fvbuf[(t - 1) & 1][b];
        float ft = ft_next;
        if (t < 511) ft_next = g_feat[t + 1][b][l];
        float best = tr[l][0] + fv[0];
        int arg = 0;
#pragma unroll
        for (int p = 1; p < 12; p++) {
            float sc = tr[l][p] + fv[p];
            if (sc > best) { best = sc; arg = p; }
        }
        fvbuf[t & 1][b][l] = best + ft;
        g_ptr[t - 1][b][l] = (unsigned char)arg;
        __syncthreads();
    }

    if (tid < 64) {
        const int bb = tid;
        float best = fvbuf[1][bb][0];
        int last = 0;
#pragma unroll
        for (int p = 1; p < 12; p++)
            if (fvbuf[1][bb][p] > best) { best = fvbuf[1][bb][p]; last = p; }
        out[bb] = best;
        float* path = out + 64 + (size_t)bb * 512;
        int cur = last;
        path[511] = (float)cur;
        for (int t = 510; t >= 0; t--) {
            cur = g_ptr[t][bb][cur];
            path[t] = (float)cur;
        }
    }
}

// ---------------------------------------------------------------------------
extern "C" void kernel_launch(void* const* d_in, const int* in_sizes, int n_in,
                              void* d_out, int out_size)
{
    const float* hs   = (const float*)d_in[0];
    const float* h0   = (const float*)d_in[1];
    const float* c0   = (const float*)d_in[2];
    const float* wihf = (const float*)d_in[3];
    const float* whhf = (const float*)d_in[4];
    const float* bihf = (const float*)d_in[5];
    const float* bhhf = (const float*)d_in[6];
    const float* wihb = (const float*)d_in[7];
    const float* whhb = (const float*)d_in[8];
    const float* bihb = (const float*)d_in[9];
    const float* bhhb = (const float*)d_in[10];
    const float* fcw  = (const float*)d_in[11];
    const float* fcb  = (const float*)d_in[12];
    const float* trans= (const float*)d_in[13];
    const int*   stp  = (const int*)d_in[14];
    (void)in_sizes; (void)n_in; (void)out_size;

    const size_t rec_smem = (size_t)REC_SMEM_FLOATS * sizeof(float); // 181,632 B
    cudaFuncSetAttribute(k_rec, cudaFuncAttributeMaxDynamicSharedMemorySize,
                         (int)rec_smem);

    k_init<<<1, 32>>>();

    dim3 gg(24, 256);   // n-tiles fastest (A-row reuse in L2)
    k_gemm<<<gg, 256>>>(hs, wihf, wihb, bihf, bhhf, bihb, bhhb);

    k_rec<<<128, 256, rec_smem>>>(whhf, whhb, h0, c0);

    k_fc<<<512, 256>>>(fcw, fcb);

    k_vit<<<1, 768>>>(trans, stp, (float*)d_out);
}

// round 13
// speedup vs baseline: 1.2261x; 1.1280x over previous
#include <cuda_runtime.h>
#include <cstdint>
#include <cstddef>

// BertBiLstmCrf: BiLSTM(768->2x384) -> FC(768->12) -> Viterbi
// B=64, T=512, H=768, LH=384, L=12. Output: [score(64); path(64*512)] f32.
// All-fp32 FFMA implementation (tensor paths unavailable/slow on this target).

#define NEGV (-1000.0f)

__device__ float        g_pre[(size_t)32768 * 3072];   // [t*64+b][dir*1536+row]
__device__ float        g_h[2][512][384][64];          // [dir][t][k][b]
__device__ float        g_feat[512][64][12];
__device__ unsigned char g_ptr[511][64][12];
__device__ unsigned int g_bar[8];

__global__ void k_init() { if (threadIdx.x < 8) g_bar[threadIdx.x] = 0u; }

// ---------------------------------------------------------------------------
// Kernel 1: input-projection SGEMM (R5 structure, forced 2 CTAs/SM).
// C[m][n] = sum_k A[m][k]*W[n][k] + bias[n],  m = t*64+b (A row = hs[b][t]),
// n<1536 -> forward weights, n>=1536 -> backward weights.
// 128x128 tile, BK=8, 256 threads, 8x8 per thread, global prefetch.
// ---------------------------------------------------------------------------
__global__ __launch_bounds__(256, 2) void k_gemm(
    const float* __restrict__ hs,
    const float* __restrict__ wf, const float* __restrict__ wb,
    const float* __restrict__ bif, const float* __restrict__ bhf,
    const float* __restrict__ bib, const float* __restrict__ bhb)
{
    __shared__ float As[8][128];
    __shared__ float Bs[8][128];
    const int tid = threadIdx.x;
    const int m0 = blockIdx.y * 128;
    const int n0 = blockIdx.x * 128;

    const int lr = tid >> 1;           // tile row 0..127
    const int lk = (tid & 1) * 4;      // k offset 0 or 4
    const int m  = m0 + lr;
    const float* arow = hs + ((size_t)(m & 63) * 512 + (m >> 6)) * 768 + lk;
    const int nrow = n0 + lr;
    const float* brow = (nrow < 1536) ? (wf + (size_t)nrow * 768 + lk)
                                      : (wb + (size_t)(nrow - 1536) * 768 + lk);

    const int ty = tid >> 4, tx = tid & 15;

    float acc[8][8];
#pragma unroll
    for (int i = 0; i < 8; i++)
#pragma unroll
        for (int j = 0; j < 8; j++) acc[i][j] = 0.f;

    float4 a4 = *(const float4*)(arow);
    float4 b4 = *(const float4*)(brow);

    for (int k0 = 0; k0 < 768; k0 += 8) {
        As[lk+0][lr] = a4.x; As[lk+1][lr] = a4.y; As[lk+2][lr] = a4.z; As[lk+3][lr] = a4.w;
        Bs[lk+0][lr] = b4.x; Bs[lk+1][lr] = b4.y; Bs[lk+2][lr] = b4.z; Bs[lk+3][lr] = b4.w;
        __syncthreads();
        if (k0 + 8 < 768) {
            a4 = *(const float4*)(arow + k0 + 8);
            b4 = *(const float4*)(brow + k0 + 8);
        }
#pragma unroll
        for (int kk = 0; kk < 8; kk++) {
            float af[8], bf[8];
            *(float4*)(af)     = *(const float4*)&As[kk][ty*8];
            *(float4*)(af + 4) = *(const float4*)&As[kk][ty*8 + 4];
            *(float4*)(bf)     = *(const float4*)&Bs[kk][tx*8];
            *(float4*)(bf + 4) = *(const float4*)&Bs[kk][tx*8 + 4];
#pragma unroll
            for (int i = 0; i < 8; i++)
#pragma unroll
                for (int j = 0; j < 8; j++)
                    acc[i][j] = fmaf(af[i], bf[j], acc[i][j]);
        }
        __syncthreads();
    }

    float bias[8];
#pragma unroll
    for (int j = 0; j < 8; j++) {
        int n = n0 + tx*8 + j;
        bias[j] = (n < 1536) ? (bif[n] + bhf[n]) : (bib[n - 1536] + bhb[n - 1536]);
    }
#pragma unroll
    for (int i = 0; i < 8; i++) {
        size_t row = (size_t)(m0 + ty*8 + i) * 3072 + (size_t)(n0 + tx*8);
        float4 v0, v1;
        v0.x = acc[i][0] + bias[0]; v0.y = acc[i][1] + bias[1];
        v0.z = acc[i][2] + bias[2]; v0.w = acc[i][3] + bias[3];
        v1.x = acc[i][4] + bias[4]; v1.y = acc[i][5] + bias[5];
        v1.z = acc[i][6] + bias[6]; v1.w = acc[i][7] + bias[7];
        *(float4*)&g_pre[row]     = v0;
        *(float4*)&g_pre[row + 4] = v1;
    }
}

// ---------------------------------------------------------------------------
// Kernel 2: persistent BiLSTM recurrence (R5 version). 128 blocks x 128 thr.
// Block = (dir, kgroup of 24 h-cols, bgroup of 16 batches); 1 block/SM.
// W_hh slice cached in smem all 512 steps; h exchanged via g_h + atomic bar.
// ---------------------------------------------------------------------------
__device__ __forceinline__ float sigf(float x) { return 1.f / (1.f + expf(-x)); }

#define REC_SMEM_FLOATS (96*388 + 384*16 + 96*17 + 384)

__device__ __forceinline__ void fma_row(float acc[4], float4 w,
                                        float4 ha, float4 hb, float4 hc, float4 hd)
{
    acc[0] = fmaf(w.w, hd.x, fmaf(w.z, hc.x, fmaf(w.y, hb.x, fmaf(w.x, ha.x, acc[0]))));
    acc[1] = fmaf(w.w, hd.y, fmaf(w.z, hc.y, fmaf(w.y, hb.y, fmaf(w.x, ha.y, acc[1]))));
    acc[2] = fmaf(w.w, hd.z, fmaf(w.z, hc.z, fmaf(w.y, hb.z, fmaf(w.x, ha.z, acc[2]))));
    acc[3] = fmaf(w.w, hd.w, fmaf(w.z, hc.w, fmaf(w.y, hb.w, fmaf(w.x, ha.w, acc[3]))));
}

__global__ __launch_bounds__(128) void k_rec(
    const float* __restrict__ whf, const float* __restrict__ whb,
    const float* __restrict__ h0, const float* __restrict__ c0)
{
    extern __shared__ float sm[];
    float* w_s    = sm;              // [96][388]
    float* h_s    = sm + 96*388;     // [384][16]
    float* gate_s = h_s + 384*16;    // [96][17]
    float* c_s    = gate_s + 96*17;  // [24*16]

    const int bid = blockIdx.x;
    const int dir = bid >> 6;
    const int kg  = (bid >> 2) & 15;
    const int bg  = bid & 3;
    const int k0  = kg * 24, b0 = bg * 16;
    const int tid = threadIdx.x;
    const float* whh = dir ? whb : whf;

    for (int idx = tid; idx < 96*96; idx += 128) {
        int r = idx / 96, cq = (idx - r*96) * 4;
        int gate = r / 24, kk = r - gate*24;
        float4 v = *(const float4*)(whh + (size_t)(gate*384 + k0 + kk) * 384 + cq);
        *(float4*)&w_s[r*388 + cq] = v;
    }
    for (int idx = tid; idx < 384; idx += 128) {
        int kk = idx >> 4, b = idx & 15;
        c_s[idx] = c0[((size_t)dir*64 + b0 + b) * 384 + k0 + kk];
    }
    __syncthreads();

    const int rg = tid >> 2;
    const int bq = tid & 3;
    const float* wr0 = w_s + (3*rg + 0) * 388;
    const float* wr1 = w_s + (3*rg + 1) * 388;
    const float* wr2 = w_s + (3*rg + 2) * 388;
    int grow[3];
#pragma unroll
    for (int i = 0; i < 3; i++) {
        int r = 3*rg + i;
        grow[i] = dir*1536 + (r/24)*384 + k0 + (r - (r/24)*24);
    }
    volatile unsigned int* bar = &g_bar[dir*4 + bg];

    float acc[3][4];
    {
        const int t0 = dir ? 511 : 0;
#pragma unroll
        for (int i = 0; i < 3; i++)
#pragma unroll
            for (int j = 0; j < 4; j++)
                acc[i][j] = g_pre[((size_t)t0*64 + b0 + 4*bq + j) * 3072 + grow[i]];
    }

    for (int s = 0; s < 512; s++) {
        const int t = dir ? (511 - s) : s;
        if (s == 0) {
            for (int idx = tid; idx < 384*16; idx += 128) {
                int k = idx >> 4, b = idx & 15;
                h_s[idx] = h0[((size_t)dir*64 + b0 + b) * 384 + k];
            }
        } else {
            const int tp = dir ? (t + 1) : (t - 1);
            const float* hp = &g_h[dir][tp][0][b0];
            for (int idx = tid; idx < 384*4; idx += 128) {
                int k = idx >> 2, q = idx & 3;
                float4 v = *(const float4*)(hp + (size_t)k*64 + q*4);
                *(float4*)&h_s[k*16 + q*4] = v;
            }
        }
        __syncthreads();

#pragma unroll 2
        for (int k = 0; k < 384; k += 4) {
            float4 w0 = *(const float4*)(wr0 + k);
            float4 w1 = *(const float4*)(wr1 + k);
            float4 w2 = *(const float4*)(wr2 + k);
            float4 ha = *(const float4*)&h_s[(k+0)*16 + bq*4];
            float4 hb = *(const float4*)&h_s[(k+1)*16 + bq*4];
            float4 hc = *(const float4*)&h_s[(k+2)*16 + bq*4];
            float4 hd = *(const float4*)&h_s[(k+3)*16 + bq*4];
            fma_row(acc[0], w0, ha, hb, hc, hd);
            fma_row(acc[1], w1, ha, hb, hc, hd);
            fma_row(acc[2], w2, ha, hb, hc, hd);
        }
#pragma unroll
        for (int i = 0; i < 3; i++)
#pragma unroll
            for (int j = 0; j < 4; j++)
                gate_s[(3*rg + i)*17 + 4*bq + j] = acc[i][j];
        __syncthreads();

        for (int idx = tid; idx < 384; idx += 128) {
            int kk = idx >> 4, b = idx & 15;
            float gi = gate_s[(kk     )*17 + b];
            float gf = gate_s[(kk + 24)*17 + b];
            float gg = gate_s[(kk + 48)*17 + b];
            float go = gate_s[(kk + 72)*17 + b];
            float c = sigf(gf) * c_s[idx] + sigf(gi) * tanhf(gg);
            c_s[idx] = c;
            g_h[dir][t][k0 + kk][b0 + b] = sigf(go) * tanhf(c);
        }
        __threadfence();
        __syncthreads();

        if (tid == 0) atomicAdd((unsigned int*)&g_bar[dir*4 + bg], 1u);

        if (s + 1 < 512) {
            const int tn = dir ? (510 - s) : (s + 1);
#pragma unroll
            for (int i = 0; i < 3; i++)
#pragma unroll
                for (int j = 0; j < 4; j++)
                    acc[i][j] = g_pre[((size_t)tn*64 + b0 + 4*bq + j) * 3072 + grow[i]];
        }
        if (tid == 0) {
            const unsigned int target = 16u * (unsigned)(s + 1);
            while (*bar < target) { }
            __threadfence();
        }
        __syncthreads();
    }
}

// ---------------------------------------------------------------------------
// Kernel 3: emissions (4 independent accumulator chains)
// ---------------------------------------------------------------------------
__global__ __launch_bounds__(256) void k_fc(const float* __restrict__ fcw,
                                            const float* __restrict__ fcb)
{
    __shared__ float wsh[12*768];
    __shared__ float bsh[12];
    const int t = blockIdx.x;
    const int tid = threadIdx.x;
    for (int i = tid; i < 12*768; i += 256) wsh[i] = fcw[i];
    if (tid < 12) bsh[tid] = fcb[tid];
    __syncthreads();

    for (int o = tid; o < 768; o += 256) {
        int l = o >> 6, b = o & 63;
        const float* wl  = &wsh[l*768];
        const float* hp0 = &g_h[0][t][0][b];
        const float* hp1 = &g_h[1][t][0][b];
        float s0 = 0.f, s1 = 0.f, s2 = 0.f, s3 = 0.f;
#pragma unroll 4
        for (int k = 0; k < 384; k += 4) {
            s0 = fmaf(hp0[(size_t)(k+0)*64], wl[k+0], s0);
            s1 = fmaf(hp0[(size_t)(k+1)*64], wl[k+1], s1);
            s2 = fmaf(hp0[(size_t)(k+2)*64], wl[k+2], s2);
            s3 = fmaf(hp0[(size_t)(k+3)*64], wl[k+3], s3);
        }
#pragma unroll 4
        for (int k = 0; k < 384; k += 4) {
            s0 = fmaf(hp1[(size_t)(k+0)*64], wl[384+k+0], s0);
            s1 = fmaf(hp1[(size_t)(k+1)*64], wl[384+k+1], s1);
            s2 = fmaf(hp1[(size_t)(k+2)*64], wl[384+k+2], s2);
            s3 = fmaf(hp1[(size_t)(k+3)*64], wl[384+k+3], s3);
        }
        g_feat[t][b][l] = bsh[l] + ((s0 + s1) + (s2 + s3));
    }
}

// ---------------------------------------------------------------------------
// Kernel 4: Viterbi forward + backtrace (1 block, 768 threads)
// ---------------------------------------------------------------------------
__global__ __launch_bounds__(768) void k_vit(const float* __restrict__ trans,
                                             const int* __restrict__ start_idx,
                                             float* __restrict__ out)
{
    __shared__ float fvbuf[2][64][12];
    __shared__ float tr[12][12];
    const int tid = threadIdx.x;
    const int b = tid / 12, l = tid - b*12;

    if (tid < 144) tr[tid / 12][tid % 12] = trans[tid];
    const int s0 = *start_idx;
    fvbuf[0][b][l] = (l == s0) ? 0.f : NEGV;
    __syncthreads();

    float ft_next = g_feat[1][b][l];
    for (int t = 1; t < 512; t++) {
        const float* fv = fvbuf[(t - 1) & 1][b];
        float ft = ft_next;
        if (t < 511) ft_next = g_feat[t + 1][b][l];
        float best = tr[l][0] + fv[0];
        int arg = 0;
#pragma unroll
        for (int p = 1; p < 12; p++) {
            float sc = tr[l][p] + fv[p];
            if (sc > best) { best = sc; arg = p; }
        }
        fvbuf[t & 1][b][l] = best + ft;
        g_ptr[t - 1][b][l] = (unsigned char)arg;
        __syncthreads();
    }

    if (tid < 64) {
        const int bb = tid;
        float best = fvbuf[1][bb][0];
        int last = 0;
#pragma unroll
        for (int p = 1; p < 12; p++)
            if (fvbuf[1][bb][p] > best) { best = fvbuf[1][bb][p]; last = p; }
        out[bb] = best;
        float* path = out + 64 + (size_t)bb * 512;
        int cur = last;
        path[511] = (float)cur;
        for (int t = 510; t >= 0; t--) {
            cur = g_ptr[t][bb][cur];
            path[t] = (float)cur;
        }
    }
}

// ---------------------------------------------------------------------------
extern "C" void kernel_launch(void* const* d_in, const int* in_sizes, int n_in,
                              void* d_out, int out_size)
{
    const float* hs   = (const float*)d_in[0];
    const float* h0   = (const float*)d_in[1];
    const float* c0   = (const float*)d_in[2];
    const float* wihf = (const float*)d_in[3];
    const float* whhf = (const float*)d_in[4];
    const float* bihf = (const float*)d_in[5];
    const float* bhhf = (const float*)d_in[6];
    const float* wihb = (const float*)d_in[7];
    const float* whhb = (const float*)d_in[8];
    const float* bihb = (const float*)d_in[9];
    const float* bhhb = (const float*)d_in[10];
    const float* fcw  = (const float*)d_in[11];
    const float* fcb  = (const float*)d_in[12];
    const float* trans= (const float*)d_in[13];
    const int*   stp  = (const int*)d_in[14];
    (void)in_sizes; (void)n_in; (void)out_size;

    const size_t rec_smem = (size_t)REC_SMEM_FLOATS * sizeof(float); // 181,632 B
    cudaFuncSetAttribute(k_rec, cudaFuncAttributeMaxDynamicSharedMemorySize,
                         (int)rec_smem);

    k_init<<<1, 32>>>();

    dim3 gg(24, 256);   // n-tiles fastest (A-row reuse in L2)
    k_gemm<<<gg, 256>>>(hs, wihf, wihb, bihf, bhhf, bihb, bhhb);

    k_rec<<<128, 128, rec_smem>>>(whhf, whhb, h0, c0);

    k_fc<<<512, 256>>>(fcw, fcb);

    k_vit<<<1, 768>>>(trans, stp, (float*)d_out);
}